// round 13
// baseline (speedup 1.0000x reference)
#include <cuda_runtime.h>
#include <cuda_fp16.h>

// deeds_graph: N=10000 volumes of 13^3, K=8 neighbors.
// 4 volumes (= 2 half2 pairs) per 768-thread block; both pairs run the smooth
// rounds in lockstep sharing all __syncthreads (halves per-pair barrier cost).
// S1 = smooth(a1 + a0*cost); c2 = a4 + a2*(a1+a0*cost) + a3*gatherW(S1)/norm;
// S2 = smooth(c2); out = a5*gatherW(S2)/norm.
// smooth = edge-pad(3) -> max3^3 -> (5-tap [1,2,3,2,1]/9)^3 (separable).
// Cross-thread passes: 4 smem rounds on z-contiguous rows, stride 20 half2 (80B)
// -> LDS.128/STS.128 conflict-free. z-passes in registers.

#define NVOX 2197          // 13^3
#define VPAD 2208          // padded halves per volume (16B chunks)
#define NCHUNK 276         // VPAD/8
#define NMAX 10000
#define KNN  8
#define NROW 361           // 19*19 padded rows
#define XROW 20            // half2 words per row (80B)
#define XCHW (NROW*XROW)   // 7220 half2 per pair
#define PT   384           // threads per pair
#define NTH  768           // block = 2 pairs
#define SMEM_H2 (2*XCHW + 2*VPAD)          // 19312 half2
#define SMEM_BYTES (SMEM_H2*4)             // 77248 B
#define CT 576             // kernel C block

__device__ __half g_S1[(size_t)NMAX * VPAD];
__device__ __half g_S2[(size_t)NMAX * VPAD];

__device__ __forceinline__ unsigned h2u(__half2 v) { return *reinterpret_cast<unsigned*>(&v); }
__device__ __forceinline__ __half2 u2h(unsigned u) { return *reinterpret_cast<__half2*>(&u); }
__device__ __forceinline__ uint4 pk4(__half2 a, __half2 b, __half2 c, __half2 d) {
    return make_uint4(h2u(a), h2u(b), h2u(c), h2u(d));
}
__device__ __forceinline__ __half2 hmax3(__half2 a, __half2 b, __half2 c) {
    return __hmax2(__hmax2(a, b), c);
}

__device__ __forceinline__ void write17(__half2* rp, const __half2 a[17]) {
    uint4* p = reinterpret_cast<uint4*>(rp);
    p[0] = pk4(a[0], a[1], a[2], a[3]);
    p[1] = pk4(a[4], a[5], a[6], a[7]);
    p[2] = pk4(a[8], a[9], a[10], a[11]);
    p[3] = pk4(a[12], a[13], a[14], a[15]);
    reinterpret_cast<unsigned*>(rp)[16] = h2u(a[16]);
}
__device__ __forceinline__ void write13(__half2* rp, const __half2 c[13]) {
    uint4* p = reinterpret_cast<uint4*>(rp);
    p[0] = pk4(c[0], c[1], c[2], c[3]);
    p[1] = pk4(c[4], c[5], c[6], c[7]);
    p[2] = pk4(c[8], c[9], c[10], c[11]);
    reinterpret_cast<unsigned*>(rp)[12] = h2u(c[12]);
}
__device__ __forceinline__ void maxrow17(__half2 a[17], const __half2* base) {
    const uint4* p = reinterpret_cast<const uint4*>(base);
    uint4 v;
    v = p[0];
    a[0]=__hmax2(a[0],u2h(v.x)); a[1]=__hmax2(a[1],u2h(v.y));
    a[2]=__hmax2(a[2],u2h(v.z)); a[3]=__hmax2(a[3],u2h(v.w));
    v = p[1];
    a[4]=__hmax2(a[4],u2h(v.x)); a[5]=__hmax2(a[5],u2h(v.y));
    a[6]=__hmax2(a[6],u2h(v.z)); a[7]=__hmax2(a[7],u2h(v.w));
    v = p[2];
    a[8]=__hmax2(a[8],u2h(v.x)); a[9]=__hmax2(a[9],u2h(v.y));
    a[10]=__hmax2(a[10],u2h(v.z)); a[11]=__hmax2(a[11],u2h(v.w));
    v = p[3];
    a[12]=__hmax2(a[12],u2h(v.x)); a[13]=__hmax2(a[13],u2h(v.y));
    a[14]=__hmax2(a[14],u2h(v.z)); a[15]=__hmax2(a[15],u2h(v.w));
    a[16]=__hmax2(a[16], base[16]);
}
__device__ __forceinline__ void addrow13(__half2 c[13], const __half2* base) {
    const uint4* p = reinterpret_cast<const uint4*>(base);
    uint4 v;
    v = p[0];
    c[0]=__hadd2(c[0],u2h(v.x)); c[1]=__hadd2(c[1],u2h(v.y));
    c[2]=__hadd2(c[2],u2h(v.z)); c[3]=__hadd2(c[3],u2h(v.w));
    v = p[1];
    c[4]=__hadd2(c[4],u2h(v.x)); c[5]=__hadd2(c[5],u2h(v.y));
    c[6]=__hadd2(c[6],u2h(v.z)); c[7]=__hadd2(c[7],u2h(v.w));
    v = p[2];
    c[8]=__hadd2(c[8],u2h(v.x)); c[9]=__hadd2(c[9],u2h(v.y));
    c[10]=__hadd2(c[10],u2h(v.z)); c[11]=__hadd2(c[11],u2h(v.w));
    c[12]=__hadd2(c[12], base[12]);
}
__device__ __forceinline__ void fmarow13(__half2 c[13], const __half2* base, __half2 m) {
    const uint4* p = reinterpret_cast<const uint4*>(base);
    uint4 v;
    v = p[0];
    c[0]=__hfma2(m,u2h(v.x),c[0]); c[1]=__hfma2(m,u2h(v.y),c[1]);
    c[2]=__hfma2(m,u2h(v.z),c[2]); c[3]=__hfma2(m,u2h(v.w),c[3]);
    v = p[1];
    c[4]=__hfma2(m,u2h(v.x),c[4]); c[5]=__hfma2(m,u2h(v.y),c[5]);
    c[6]=__hfma2(m,u2h(v.z),c[6]); c[7]=__hfma2(m,u2h(v.w),c[7]);
    v = p[2];
    c[8]=__hfma2(m,u2h(v.x),c[8]); c[9]=__hfma2(m,u2h(v.y),c[9]);
    c[10]=__hfma2(m,u2h(v.z),c[10]); c[11]=__hfma2(m,u2h(v.w),c[11]);
    c[12]=__hfma2(m, base[12], c[12]);
}

// col: 19 padded-z half2 of row (x,y)=(tt%19,tt/19). Result -> outb[(x*13+y)*13+z].
// Syncs are block-wide (both pairs in lockstep).
__device__ __forceinline__ void smooth_rounds(__half2 col[19], __half2* xch,
                                              __half2* outb, int tt) {
    const __half2 T2 = __float2half2_rn(2.0f);
    const __half2 T3 = __float2half2_rn(3.0f);
    const __half2 INV = __float2half2_rn(1.0f/729.0f);
    int x = tt % 19, y = tt / 19;
    bool own = tt < NROW;
    __half2* myrow = xch + tt * XROW;

    __half2 a[17];
    #pragma unroll
    for (int z = 0; z < 17; z++) a[z] = hmax3(col[z], col[z+1], col[z+2]);

    // R1: max over x
    if (own) write17(myrow, a);
    __syncthreads();
    if (own && x < 17) {
        maxrow17(a, xch + (tt+1)*XROW);
        maxrow17(a, xch + (tt+2)*XROW);
    }
    __syncthreads();

    // R2: max over y
    if (own) write17(myrow, a);
    __syncthreads();
    if (own && y < 17) {
        maxrow17(a, xch + (tt+19)*XROW);
        maxrow17(a, xch + (tt+38)*XROW);
    }
    __syncthreads();

    // 5-tap over z (registers)
    __half2 c[13];
    #pragma unroll
    for (int z = 0; z < 13; z++) {
        __half2 s = __hadd2(a[z], a[z+4]);
        s = __hfma2(T2, __hadd2(a[z+1], a[z+3]), s);
        c[z] = __hfma2(T3, a[z+2], s);
    }

    // R3: 5-tap over x
    if (own) write13(myrow, c);
    __syncthreads();
    if (own && x < 13) {
        fmarow13(c, xch + (tt+1)*XROW, T2);
        fmarow13(c, xch + (tt+2)*XROW, T3);
        fmarow13(c, xch + (tt+3)*XROW, T2);
        addrow13(c, xch + (tt+4)*XROW);
    }
    __syncthreads();

    // R4: 5-tap over y + final write
    if (own) write13(myrow, c);
    __syncthreads();
    if (own && x < 13 && y < 13) {
        fmarow13(c, xch + (tt+19)*XROW, T2);
        fmarow13(c, xch + (tt+38)*XROW, T3);
        fmarow13(c, xch + (tt+57)*XROW, T2);
        addrow13(c, xch + (tt+76)*XROW);
        int base = (x*13 + y)*13;
        #pragma unroll
        for (int z = 0; z < 13; z++) outb[base + z] = __hmul2(c[z], INV);
    }
}

__device__ __forceinline__ void build_col(const __half2* lin, __half2 col[19], int tt) {
    if (tt < NROW) {
        int x = tt % 19, y = tt / 19;
        int cx = min(max(x - 3, 0), 12);
        int cy = min(max(y - 3, 0), 12);
        const __half2* src = lin + (cx*13 + cy)*13;
        __half2 vv[13];
        #pragma unroll
        for (int z = 0; z < 13; z++) vv[z] = src[z];
        #pragma unroll
        for (int pz = 0; pz < 19; pz++) col[pz] = vv[min(max(pz - 3, 0), 12)];
    }
}

__device__ __forceinline__ void store_pair(const __half2* outb, __half* d0, __half* d1,
                                           int tt) {
    const __half2 Z = __float2half2_rn(0.0f);
    for (int i = tt; i < VPAD/2; i += PT) {
        int i0 = 2*i;
        __half2 v0 = (i0     < NVOX) ? outb[i0]     : Z;
        __half2 v1 = (i0 + 1 < NVOX) ? outb[i0 + 1] : Z;
        *reinterpret_cast<__half2*>(d0 + i0) = __lows2half2(v0, v1);
        *reinterpret_cast<__half2*>(d1 + i0) = __highs2half2(v0, v1);
    }
}

// ------------- Kernel A: S1 = smooth(a1 + a0*cost), 2 pairs/block -------------
__global__ void __launch_bounds__(NTH, 2) k_smooth1(
    const float* __restrict__ cost, const float* __restrict__ alpha) {
    extern __shared__ __align__(16) __half2 sm[];
    int t = threadIdx.x;
    int sub = t / PT, tt = t - sub*PT;
    __half2* xch = sm + sub*XCHW;
    __half2* lin = sm + 2*XCHW + sub*VPAD;
    int p = blockIdx.x*2 + sub;
    float a0 = alpha[0], a1 = alpha[1];
    const float* s0 = cost + (size_t)(2*p) * NVOX;
    const float* s1 = cost + (size_t)(2*p + 1) * NVOX;

    for (int v = tt; v < NVOX; v += PT)
        lin[v] = __floats2half2_rn(a1 + a0 * __ldg(s0 + v), a1 + a0 * __ldg(s1 + v));
    __syncthreads();

    __half2 col[19];
    build_col(lin, col, tt);
    smooth_rounds(col, xch, lin, tt);   // outb reuses lin (all lin reads pre-R1)
    __syncthreads();
    store_pair(lin, g_S1 + (size_t)(2*p)*VPAD, g_S1 + (size_t)(2*p+1)*VPAD, tt);
}

// --- Kernel B: c2 = blend(cost, gatherW(S1)); S2 = smooth(c2), 2 pairs/block ---
__global__ void __launch_bounds__(NTH, 2) k_gather_smooth(
    const float* __restrict__ cost, const int* __restrict__ knn,
    const float* __restrict__ dist, const float* __restrict__ alpha) {
    extern __shared__ __align__(16) __half2 sm[];
    __shared__ float wsh[4][KNN];
    __shared__ int   nbsh[4][KNN];
    __shared__ float sninv[4];
    int t = threadIdx.x;
    int sub = t / PT, tt = t - sub*PT;
    __half2* xch = sm + sub*XCHW;
    __half2* lin = sm + 2*XCHW + sub*VPAD;
    int p = blockIdx.x*2 + sub;

    if (t < 32) {                 // 4 volumes x 8 weights in parallel
        int h = t >> 3, k = t & 7;
        int n = 4*blockIdx.x + h;
        wsh[h][k] = __expf(-__ldg(&dist[n*KNN + k]) * (1.0f/200.0f)); // 2*SIGMA^2=200
        nbsh[h][k] = __ldg(&knn[n*KNN + k]);
    }
    __syncthreads();
    if (t < 4) {
        float s = 0.0f;
        #pragma unroll
        for (int k = 0; k < KNN; k++) s += wsh[t][k];
        sninv[t] = 1.0f / s;
    }
    __syncthreads();

    float a0 = alpha[0], a1 = alpha[1], a2 = alpha[2], a3 = alpha[3], a4 = alpha[4];

    // 552 threads: one (pair g, chunk) each, both volumes of that pair (16 LDG.128)
    if (t < 2*NCHUNK) {
        int g = t / NCHUNK;
        int cch = t - g*NCHUNK;
        int vbase = cch * 8;
        int pg = blockIdx.x*2 + g;
        __half2* ling = sm + 2*XCHW + g*VPAD;
        float res[2][8];
        #pragma unroll
        for (int h = 0; h < 2; h++) {
            int vol = 2*g + h;       // volume index within block (0..3)
            float acc[8];
            #pragma unroll
            for (int j = 0; j < 8; j++) acc[j] = 0.0f;
            #pragma unroll
            for (int k = 0; k < KNN; k++) {
                float w = wsh[vol][k];
                const uint4* np = reinterpret_cast<const uint4*>(
                    g_S1 + (size_t)nbsh[vol][k] * VPAD);
                uint4 raw = __ldg(&np[cch]);
                float2 f0 = __half22float2(u2h(raw.x));
                float2 f1 = __half22float2(u2h(raw.y));
                float2 f2 = __half22float2(u2h(raw.z));
                float2 f3 = __half22float2(u2h(raw.w));
                acc[0] += w*f0.x; acc[1] += w*f0.y;
                acc[2] += w*f1.x; acc[3] += w*f1.y;
                acc[4] += w*f2.x; acc[5] += w*f2.y;
                acc[6] += w*f3.x; acc[7] += w*f3.y;
            }
            const float* src = cost + (size_t)(2*pg + h) * NVOX;
            float ninv = sninv[vol];
            #pragma unroll
            for (int j = 0; j < 8; j++) {
                int v = vbase + j;
                float c1 = (v < NVOX) ? (a1 + a0 * __ldg(&src[v])) : 0.0f;
                res[h][j] = a4 + a2*c1 + a3*(acc[j]*ninv);
            }
        }
        uint4 w0, w1;
        w0.x = h2u(__floats2half2_rn(res[0][0], res[1][0]));
        w0.y = h2u(__floats2half2_rn(res[0][1], res[1][1]));
        w0.z = h2u(__floats2half2_rn(res[0][2], res[1][2]));
        w0.w = h2u(__floats2half2_rn(res[0][3], res[1][3]));
        w1.x = h2u(__floats2half2_rn(res[0][4], res[1][4]));
        w1.y = h2u(__floats2half2_rn(res[0][5], res[1][5]));
        w1.z = h2u(__floats2half2_rn(res[0][6], res[1][6]));
        w1.w = h2u(__floats2half2_rn(res[0][7], res[1][7]));
        uint4* lp = reinterpret_cast<uint4*>(ling);
        lp[cch*2]     = w0;
        lp[cch*2 + 1] = w1;
    }
    __syncthreads();

    __half2 col[19];
    build_col(lin, col, tt);
    smooth_rounds(col, xch, lin, tt);
    __syncthreads();
    store_pair(lin, g_S2 + (size_t)(2*p)*VPAD, g_S2 + (size_t)(2*p+1)*VPAD, tt);
}

// ------- Kernel C: out = a5 * gatherW(S2) / norm, paired + coalesced stores -------
__global__ void __launch_bounds__(CT) k_gather_out(
    const int* __restrict__ knn, const float* __restrict__ dist,
    const float* __restrict__ alpha, float* __restrict__ out) {
    __shared__ float wsh[2][KNN];
    __shared__ int   nbsh[2][KNN];
    __shared__ float sscale[2];
    __shared__ float obuf[2][VPAD];
    int p = blockIdx.x;
    int tid = threadIdx.x;

    if (tid < 16) {
        int h = tid >> 3, k = tid & 7;
        int n = 2*p + h;
        wsh[h][k] = __expf(-__ldg(&dist[n*KNN + k]) * (1.0f/200.0f));
        nbsh[h][k] = __ldg(&knn[n*KNN + k]);
    }
    __syncthreads();
    if (tid < 2) {
        float s = 0.0f;
        #pragma unroll
        for (int k = 0; k < KNN; k++) s += wsh[tid][k];
        sscale[tid] = alpha[5] / s;
    }
    __syncthreads();

    if (tid < 2*NCHUNK) {
        int h = tid / NCHUNK;
        int cch = tid - h*NCHUNK;
        float acc[8];
        #pragma unroll
        for (int j = 0; j < 8; j++) acc[j] = 0.0f;
        #pragma unroll
        for (int k = 0; k < KNN; k++) {
            float w = wsh[h][k];
            const uint4* np = reinterpret_cast<const uint4*>(
                g_S2 + (size_t)nbsh[h][k] * VPAD);
            uint4 raw = __ldg(&np[cch]);
            float2 f0 = __half22float2(u2h(raw.x));
            float2 f1 = __half22float2(u2h(raw.y));
            float2 f2 = __half22float2(u2h(raw.z));
            float2 f3 = __half22float2(u2h(raw.w));
            acc[0] += w*f0.x; acc[1] += w*f0.y;
            acc[2] += w*f1.x; acc[3] += w*f1.y;
            acc[4] += w*f2.x; acc[5] += w*f2.y;
            acc[6] += w*f3.x; acc[7] += w*f3.y;
        }
        float sc = sscale[h];
        int vbase = cch * 8;
        #pragma unroll
        for (int j = 0; j < 8; j++) obuf[h][vbase + j] = acc[j] * sc;
    }
    __syncthreads();

    float* d0 = out + (size_t)(2*p) * NVOX;
    float* d1 = out + (size_t)(2*p + 1) * NVOX;
    for (int i = tid; i < NVOX; i += CT) {
        d0[i] = obuf[0][i];
        d1[i] = obuf[1][i];
    }
}

extern "C" void kernel_launch(void* const* d_in, const int* in_sizes, int n_in,
                              void* d_out, int out_size) {
    const float* cost  = (const float*)d_in[0];
    const int*   knn   = (const int*)d_in[1];
    const float* dist  = (const float*)d_in[2];
    const float* alpha = (const float*)d_in[3];
    float* out = (float*)d_out;
    int N = in_sizes[0] / NVOX;   // 10000
    int NP = N / 2;               // 5000 pairs
    int NQ = NP / 2;              // 2500 blocks of 2 pairs

    cudaFuncSetAttribute(k_smooth1, cudaFuncAttributeMaxDynamicSharedMemorySize, SMEM_BYTES);
    cudaFuncSetAttribute(k_gather_smooth, cudaFuncAttributeMaxDynamicSharedMemorySize, SMEM_BYTES);

    k_smooth1<<<NQ, NTH, SMEM_BYTES>>>(cost, alpha);
    k_gather_smooth<<<NQ, NTH, SMEM_BYTES>>>(cost, knn, dist, alpha);
    k_gather_out<<<NP, CT>>>(knn, dist, alpha, out);
}

// round 15
// speedup vs baseline: 1.0190x; 1.0190x over previous
#include <cuda_runtime.h>
#include <cuda_fp16.h>

// deeds_graph: N=10000 volumes of 13^3, K=8 neighbors. One half2 pair per
// 384-thread block (R12 structure — small independent blocks won over R13's
// 768-thread lockstep). lin buffer ALIASED into xch (build_col snapshots to
// registers; output written after a drain barrier) -> smem 28.9KB, and
// __launch_bounds__(384,5) caps regs for 5 blocks/SM (~94% occ).
// S1 = smooth(a1 + a0*cost); c2 = a4 + a2*(a1+a0*cost) + a3*gatherW(S1)/norm;
// S2 = smooth(c2); out = a5*gatherW(S2)/norm.
// smooth = edge-pad(3) -> max3^3 -> (5-tap [1,2,3,2,1]/9)^3 (separable).
// Cross-thread passes: 4 smem rounds on z-contiguous rows, stride 20 half2
// (80B) -> LDS.128/STS.128 conflict-free. z-passes in registers.

#define NVOX 2197          // 13^3
#define VPAD 2208          // padded halves per volume (16B chunks)
#define NCHUNK 276         // VPAD/8
#define NMAX 10000
#define KNN  8
#define NROW 361           // 19*19 padded rows
#define XROW 20            // half2 words per row (80B)
#define XCHW (NROW*XROW)   // 7220 half2 (28.9KB) — also holds lin[VPAD] aliased
#define PT   384           // threads per block
#define CT 576             // kernel C block

__device__ __half g_S1[(size_t)NMAX * VPAD];
__device__ __half g_S2[(size_t)NMAX * VPAD];

__device__ __forceinline__ unsigned h2u(__half2 v) { return *reinterpret_cast<unsigned*>(&v); }
__device__ __forceinline__ __half2 u2h(unsigned u) { return *reinterpret_cast<__half2*>(&u); }
__device__ __forceinline__ uint4 pk4(__half2 a, __half2 b, __half2 c, __half2 d) {
    return make_uint4(h2u(a), h2u(b), h2u(c), h2u(d));
}
__device__ __forceinline__ __half2 hmax3(__half2 a, __half2 b, __half2 c) {
    return __hmax2(__hmax2(a, b), c);
}

__device__ __forceinline__ void write17(__half2* rp, const __half2 a[17]) {
    uint4* p = reinterpret_cast<uint4*>(rp);
    p[0] = pk4(a[0], a[1], a[2], a[3]);
    p[1] = pk4(a[4], a[5], a[6], a[7]);
    p[2] = pk4(a[8], a[9], a[10], a[11]);
    p[3] = pk4(a[12], a[13], a[14], a[15]);
    reinterpret_cast<unsigned*>(rp)[16] = h2u(a[16]);
}
__device__ __forceinline__ void write13(__half2* rp, const __half2 c[13]) {
    uint4* p = reinterpret_cast<uint4*>(rp);
    p[0] = pk4(c[0], c[1], c[2], c[3]);
    p[1] = pk4(c[4], c[5], c[6], c[7]);
    p[2] = pk4(c[8], c[9], c[10], c[11]);
    reinterpret_cast<unsigned*>(rp)[12] = h2u(c[12]);
}
__device__ __forceinline__ void maxrow17(__half2 a[17], const __half2* base) {
    const uint4* p = reinterpret_cast<const uint4*>(base);
    uint4 v;
    v = p[0];
    a[0]=__hmax2(a[0],u2h(v.x)); a[1]=__hmax2(a[1],u2h(v.y));
    a[2]=__hmax2(a[2],u2h(v.z)); a[3]=__hmax2(a[3],u2h(v.w));
    v = p[1];
    a[4]=__hmax2(a[4],u2h(v.x)); a[5]=__hmax2(a[5],u2h(v.y));
    a[6]=__hmax2(a[6],u2h(v.z)); a[7]=__hmax2(a[7],u2h(v.w));
    v = p[2];
    a[8]=__hmax2(a[8],u2h(v.x)); a[9]=__hmax2(a[9],u2h(v.y));
    a[10]=__hmax2(a[10],u2h(v.z)); a[11]=__hmax2(a[11],u2h(v.w));
    v = p[3];
    a[12]=__hmax2(a[12],u2h(v.x)); a[13]=__hmax2(a[13],u2h(v.y));
    a[14]=__hmax2(a[14],u2h(v.z)); a[15]=__hmax2(a[15],u2h(v.w));
    a[16]=__hmax2(a[16], base[16]);
}
__device__ __forceinline__ void addrow13(__half2 c[13], const __half2* base) {
    const uint4* p = reinterpret_cast<const uint4*>(base);
    uint4 v;
    v = p[0];
    c[0]=__hadd2(c[0],u2h(v.x)); c[1]=__hadd2(c[1],u2h(v.y));
    c[2]=__hadd2(c[2],u2h(v.z)); c[3]=__hadd2(c[3],u2h(v.w));
    v = p[1];
    c[4]=__hadd2(c[4],u2h(v.x)); c[5]=__hadd2(c[5],u2h(v.y));
    c[6]=__hadd2(c[6],u2h(v.z)); c[7]=__hadd2(c[7],u2h(v.w));
    v = p[2];
    c[8]=__hadd2(c[8],u2h(v.x)); c[9]=__hadd2(c[9],u2h(v.y));
    c[10]=__hadd2(c[10],u2h(v.z)); c[11]=__hadd2(c[11],u2h(v.w));
    c[12]=__hadd2(c[12], base[12]);
}
__device__ __forceinline__ void fmarow13(__half2 c[13], const __half2* base, __half2 m) {
    const uint4* p = reinterpret_cast<const uint4*>(base);
    uint4 v;
    v = p[0];
    c[0]=__hfma2(m,u2h(v.x),c[0]); c[1]=__hfma2(m,u2h(v.y),c[1]);
    c[2]=__hfma2(m,u2h(v.z),c[2]); c[3]=__hfma2(m,u2h(v.w),c[3]);
    v = p[1];
    c[4]=__hfma2(m,u2h(v.x),c[4]); c[5]=__hfma2(m,u2h(v.y),c[5]);
    c[6]=__hfma2(m,u2h(v.z),c[6]); c[7]=__hfma2(m,u2h(v.w),c[7]);
    v = p[2];
    c[8]=__hfma2(m,u2h(v.x),c[8]); c[9]=__hfma2(m,u2h(v.y),c[9]);
    c[10]=__hfma2(m,u2h(v.z),c[10]); c[11]=__hfma2(m,u2h(v.w),c[11]);
    c[12]=__hfma2(m, base[12], c[12]);
}

// col in registers; xch also serves as lin (entry barrier drains lin reads
// before R1 overwrites) and as outb (pre-output barrier drains R4 row reads).
__device__ __forceinline__ void smooth_rounds(__half2 col[19], __half2* xch, int t) {
    const __half2 T2 = __float2half2_rn(2.0f);
    const __half2 T3 = __float2half2_rn(3.0f);
    const __half2 INV = __float2half2_rn(1.0f/729.0f);
    int x = t % 19, y = t / 19;
    bool own = t < NROW;
    __half2* myrow = xch + t * XROW;

    __half2 a[17];
    #pragma unroll
    for (int z = 0; z < 17; z++) a[z] = hmax3(col[z], col[z+1], col[z+2]);

    __syncthreads();   // drain lin reads (xch aliased)

    // R1: max over x
    if (own) write17(myrow, a);
    __syncthreads();
    if (own && x < 17) {
        maxrow17(a, xch + (t+1)*XROW);
        maxrow17(a, xch + (t+2)*XROW);
    }
    __syncthreads();

    // R2: max over y
    if (own) write17(myrow, a);
    __syncthreads();
    if (own && y < 17) {
        maxrow17(a, xch + (t+19)*XROW);
        maxrow17(a, xch + (t+38)*XROW);
    }
    __syncthreads();

    // 5-tap over z (registers)
    __half2 c[13];
    #pragma unroll
    for (int z = 0; z < 13; z++) {
        __half2 s = __hadd2(a[z], a[z+4]);
        s = __hfma2(T2, __hadd2(a[z+1], a[z+3]), s);
        c[z] = __hfma2(T3, a[z+2], s);
    }

    // R3: 5-tap over x
    if (own) write13(myrow, c);
    __syncthreads();
    if (own && x < 13) {
        fmarow13(c, xch + (t+1)*XROW, T2);
        fmarow13(c, xch + (t+2)*XROW, T3);
        fmarow13(c, xch + (t+3)*XROW, T2);
        addrow13(c, xch + (t+4)*XROW);
    }
    __syncthreads();

    // R4: 5-tap over y
    if (own) write13(myrow, c);
    __syncthreads();
    if (own && x < 13 && y < 13) {
        fmarow13(c, xch + (t+19)*XROW, T2);
        fmarow13(c, xch + (t+38)*XROW, T3);
        fmarow13(c, xch + (t+57)*XROW, T2);
        addrow13(c, xch + (t+76)*XROW);
    }
    __syncthreads();   // drain R4 row reads before output overwrites xch
    if (own && x < 13 && y < 13) {
        int base = (x*13 + y)*13;
        #pragma unroll
        for (int z = 0; z < 13; z++) xch[base + z] = __hmul2(c[z], INV);
    }
}

__device__ __forceinline__ void build_col(const __half2* lin, __half2 col[19], int t) {
    if (t < NROW) {
        int x = t % 19, y = t / 19;
        int cx = min(max(x - 3, 0), 12);
        int cy = min(max(y - 3, 0), 12);
        const __half2* src = lin + (cx*13 + cy)*13;
        __half2 vv[13];
        #pragma unroll
        for (int z = 0; z < 13; z++) vv[z] = src[z];
        #pragma unroll
        for (int pz = 0; pz < 19; pz++) col[pz] = vv[min(max(pz - 3, 0), 12)];
    }
}

__device__ __forceinline__ void store_pair(const __half2* outb, __half* d0, __half* d1,
                                           int t) {
    const __half2 Z = __float2half2_rn(0.0f);
    for (int i = t; i < VPAD/2; i += PT) {
        int i0 = 2*i;
        __half2 v0 = (i0     < NVOX) ? outb[i0]     : Z;
        __half2 v1 = (i0 + 1 < NVOX) ? outb[i0 + 1] : Z;
        *reinterpret_cast<__half2*>(d0 + i0) = __lows2half2(v0, v1);
        *reinterpret_cast<__half2*>(d1 + i0) = __highs2half2(v0, v1);
    }
}

// ---------------- Kernel A: S1 = smooth(a1 + a0*cost), paired ----------------
__global__ void __launch_bounds__(PT, 5) k_smooth1(
    const float* __restrict__ cost, const float* __restrict__ alpha) {
    __shared__ __align__(16) __half2 xch[XCHW];
    int p = blockIdx.x, t = threadIdx.x;
    float a0 = alpha[0], a1 = alpha[1];
    const float* s0 = cost + (size_t)(2*p) * NVOX;
    const float* s1 = cost + (size_t)(2*p + 1) * NVOX;

    for (int v = t; v < NVOX; v += PT)
        xch[v] = __floats2half2_rn(a1 + a0 * __ldg(s0 + v), a1 + a0 * __ldg(s1 + v));
    __syncthreads();

    __half2 col[19];
    build_col(xch, col, t);
    smooth_rounds(col, xch, t);
    __syncthreads();
    store_pair(xch, g_S1 + (size_t)(2*p)*VPAD, g_S1 + (size_t)(2*p+1)*VPAD, t);
}

// ------- Kernel B: c2 = blend(cost, gatherW(S1)); S2 = smooth(c2), paired -------
__global__ void __launch_bounds__(PT, 5) k_gather_smooth(
    const float* __restrict__ cost, const int* __restrict__ knn,
    const float* __restrict__ dist, const float* __restrict__ alpha) {
    __shared__ __align__(16) __half2 xch[XCHW];
    __shared__ float wsh[2][KNN];
    __shared__ int   nbsh[2][KNN];
    __shared__ float sninv[2];
    int p = blockIdx.x, t = threadIdx.x;

    if (t < 16) {
        int h = t >> 3, k = t & 7;
        int n = 2*p + h;
        wsh[h][k] = __expf(-__ldg(&dist[n*KNN + k]) * (1.0f/200.0f)); // 2*SIGMA^2=200
        nbsh[h][k] = __ldg(&knn[n*KNN + k]);
    }
    __syncthreads();
    if (t < 2) {
        float s = 0.0f;
        #pragma unroll
        for (int k = 0; k < KNN; k++) s += wsh[t][k];
        sninv[t] = 1.0f / s;
    }
    __syncthreads();

    float a0 = alpha[0], a1 = alpha[1], a2 = alpha[2], a3 = alpha[3], a4 = alpha[4];

    // 276 threads: one chunk (8 voxels), both volumes sequentially (regs low);
    // per-volume scalar STS.16 into interleaved half layout 2*v+h.
    if (t < NCHUNK) {
        int cch = t, vbase = cch * 8;
        __half* c2h = reinterpret_cast<__half*>(xch);
        #pragma unroll
        for (int h = 0; h < 2; h++) {
            float acc[8];
            #pragma unroll
            for (int j = 0; j < 8; j++) acc[j] = 0.0f;
            #pragma unroll
            for (int k = 0; k < KNN; k++) {
                float w = wsh[h][k];
                const uint4* np = reinterpret_cast<const uint4*>(
                    g_S1 + (size_t)nbsh[h][k] * VPAD);
                uint4 raw = __ldg(&np[cch]);
                float2 f0 = __half22float2(u2h(raw.x));
                float2 f1 = __half22float2(u2h(raw.y));
                float2 f2 = __half22float2(u2h(raw.z));
                float2 f3 = __half22float2(u2h(raw.w));
                acc[0] += w*f0.x; acc[1] += w*f0.y;
                acc[2] += w*f1.x; acc[3] += w*f1.y;
                acc[4] += w*f2.x; acc[5] += w*f2.y;
                acc[6] += w*f3.x; acc[7] += w*f3.y;
            }
            const float* src = cost + (size_t)(2*p + h) * NVOX;
            float ninv = sninv[h];
            #pragma unroll
            for (int j = 0; j < 8; j++) {
                int v = vbase + j;
                float c1 = (v < NVOX) ? (a1 + a0 * __ldg(&src[v])) : 0.0f;
                c2h[2*v + h] = __float2half_rn(a4 + a2*c1 + a3*(acc[j]*ninv));
            }
        }
    }
    __syncthreads();

    __half2 col[19];
    build_col(xch, col, t);
    smooth_rounds(col, xch, t);
    __syncthreads();
    store_pair(xch, g_S2 + (size_t)(2*p)*VPAD, g_S2 + (size_t)(2*p+1)*VPAD, t);
}

// ------- Kernel C: out = a5 * gatherW(S2) / norm, paired + coalesced stores -------
__global__ void __launch_bounds__(CT) k_gather_out(
    const int* __restrict__ knn, const float* __restrict__ dist,
    const float* __restrict__ alpha, float* __restrict__ out) {
    __shared__ float wsh[2][KNN];
    __shared__ int   nbsh[2][KNN];
    __shared__ float sscale[2];
    __shared__ float obuf[2][VPAD];
    int p = blockIdx.x;
    int tid = threadIdx.x;

    if (tid < 16) {
        int h = tid >> 3, k = tid & 7;
        int n = 2*p + h;
        wsh[h][k] = __expf(-__ldg(&dist[n*KNN + k]) * (1.0f/200.0f));
        nbsh[h][k] = __ldg(&knn[n*KNN + k]);
    }
    __syncthreads();
    if (tid < 2) {
        float s = 0.0f;
        #pragma unroll
        for (int k = 0; k < KNN; k++) s += wsh[tid][k];
        sscale[tid] = alpha[5] / s;
    }
    __syncthreads();

    if (tid < 2*NCHUNK) {
        int h = tid / NCHUNK;
        int cch = tid - h*NCHUNK;
        float acc[8];
        #pragma unroll
        for (int j = 0; j < 8; j++) acc[j] = 0.0f;
        #pragma unroll
        for (int k = 0; k < KNN; k++) {
            float w = wsh[h][k];
            const uint4* np = reinterpret_cast<const uint4*>(
                g_S2 + (size_t)nbsh[h][k] * VPAD);
            uint4 raw = __ldg(&np[cch]);
            float2 f0 = __half22float2(u2h(raw.x));
            float2 f1 = __half22float2(u2h(raw.y));
            float2 f2 = __half22float2(u2h(raw.z));
            float2 f3 = __half22float2(u2h(raw.w));
            acc[0] += w*f0.x; acc[1] += w*f0.y;
            acc[2] += w*f1.x; acc[3] += w*f1.y;
            acc[4] += w*f2.x; acc[5] += w*f2.y;
            acc[6] += w*f3.x; acc[7] += w*f3.y;
        }
        float sc = sscale[h];
        int vbase = cch * 8;
        #pragma unroll
        for (int j = 0; j < 8; j++) obuf[h][vbase + j] = acc[j] * sc;
    }
    __syncthreads();

    float* d0 = out + (size_t)(2*p) * NVOX;
    float* d1 = out + (size_t)(2*p + 1) * NVOX;
    for (int i = tid; i < NVOX; i += CT) {
        d0[i] = obuf[0][i];
        d1[i] = obuf[1][i];
    }
}

extern "C" void kernel_launch(void* const* d_in, const int* in_sizes, int n_in,
                              void* d_out, int out_size) {
    const float* cost  = (const float*)d_in[0];
    const int*   knn   = (const int*)d_in[1];
    const float* dist  = (const float*)d_in[2];
    const float* alpha = (const float*)d_in[3];
    float* out = (float*)d_out;
    int N = in_sizes[0] / NVOX;   // 10000
    int NP = N / 2;               // 5000 volume pairs

    k_smooth1<<<NP, PT>>>(cost, alpha);
    k_gather_smooth<<<NP, PT>>>(cost, knn, dist, alpha);
    k_gather_out<<<NP, CT>>>(knn, dist, alpha, out);
}

// round 16
// speedup vs baseline: 1.0901x; 1.0698x over previous
#include <cuda_runtime.h>
#include <cuda_fp16.h>

// deeds_graph: N=10000 volumes of 13^3, K=8 neighbors. One half2 pair per
// 384-thread block. lin aliased into xch (28.9KB smem). Smooth cross-thread
// passes are smem "rounds" on z-contiguous rows (stride 20 half2 = 80B,
// LDS.128/STS.128 conflict-free). NEW: the two max rounds are FUSED into one
// 3x3-neighborhood round (8 neighbor-row reads) — saves 2 barriers + 1 write
// per smooth; max fusion is bitwise identical.
// S1 = smooth(a1 + a0*cost); c2 = a4 + a2*(a1+a0*cost) + a3*gatherW(S1)/norm;
// S2 = smooth(c2); out = a5*gatherW(S2)/norm.
// smooth = edge-pad(3) -> max3^3 -> (5-tap [1,2,3,2,1]/9)^3 (separable).

#define NVOX 2197          // 13^3
#define VPAD 2208          // padded halves per volume (16B chunks)
#define NCHUNK 276         // VPAD/8
#define NMAX 10000
#define KNN  8
#define NROW 361           // 19*19 padded rows
#define XROW 20            // half2 words per row (80B)
#define XCHW (NROW*XROW)   // 7220 half2 (28.9KB), lin[VPAD] aliased in
#define PT   384           // threads per block
#define CT 576             // kernel C block

__device__ __half g_S1[(size_t)NMAX * VPAD];
__device__ __half g_S2[(size_t)NMAX * VPAD];

__device__ __forceinline__ unsigned h2u(__half2 v) { return *reinterpret_cast<unsigned*>(&v); }
__device__ __forceinline__ __half2 u2h(unsigned u) { return *reinterpret_cast<__half2*>(&u); }
__device__ __forceinline__ uint4 pk4(__half2 a, __half2 b, __half2 c, __half2 d) {
    return make_uint4(h2u(a), h2u(b), h2u(c), h2u(d));
}
__device__ __forceinline__ __half2 hmax3(__half2 a, __half2 b, __half2 c) {
    return __hmax2(__hmax2(a, b), c);
}

__device__ __forceinline__ void write17(__half2* rp, const __half2 a[17]) {
    uint4* p = reinterpret_cast<uint4*>(rp);
    p[0] = pk4(a[0], a[1], a[2], a[3]);
    p[1] = pk4(a[4], a[5], a[6], a[7]);
    p[2] = pk4(a[8], a[9], a[10], a[11]);
    p[3] = pk4(a[12], a[13], a[14], a[15]);
    reinterpret_cast<unsigned*>(rp)[16] = h2u(a[16]);
}
__device__ __forceinline__ void write13(__half2* rp, const __half2 c[13]) {
    uint4* p = reinterpret_cast<uint4*>(rp);
    p[0] = pk4(c[0], c[1], c[2], c[3]);
    p[1] = pk4(c[4], c[5], c[6], c[7]);
    p[2] = pk4(c[8], c[9], c[10], c[11]);
    reinterpret_cast<unsigned*>(rp)[12] = h2u(c[12]);
}
__device__ __forceinline__ void maxrow17(__half2 a[17], const __half2* base) {
    const uint4* p = reinterpret_cast<const uint4*>(base);
    uint4 v;
    v = p[0];
    a[0]=__hmax2(a[0],u2h(v.x)); a[1]=__hmax2(a[1],u2h(v.y));
    a[2]=__hmax2(a[2],u2h(v.z)); a[3]=__hmax2(a[3],u2h(v.w));
    v = p[1];
    a[4]=__hmax2(a[4],u2h(v.x)); a[5]=__hmax2(a[5],u2h(v.y));
    a[6]=__hmax2(a[6],u2h(v.z)); a[7]=__hmax2(a[7],u2h(v.w));
    v = p[2];
    a[8]=__hmax2(a[8],u2h(v.x)); a[9]=__hmax2(a[9],u2h(v.y));
    a[10]=__hmax2(a[10],u2h(v.z)); a[11]=__hmax2(a[11],u2h(v.w));
    v = p[3];
    a[12]=__hmax2(a[12],u2h(v.x)); a[13]=__hmax2(a[13],u2h(v.y));
    a[14]=__hmax2(a[14],u2h(v.z)); a[15]=__hmax2(a[15],u2h(v.w));
    a[16]=__hmax2(a[16], base[16]);
}
__device__ __forceinline__ void addrow13(__half2 c[13], const __half2* base) {
    const uint4* p = reinterpret_cast<const uint4*>(base);
    uint4 v;
    v = p[0];
    c[0]=__hadd2(c[0],u2h(v.x)); c[1]=__hadd2(c[1],u2h(v.y));
    c[2]=__hadd2(c[2],u2h(v.z)); c[3]=__hadd2(c[3],u2h(v.w));
    v = p[1];
    c[4]=__hadd2(c[4],u2h(v.x)); c[5]=__hadd2(c[5],u2h(v.y));
    c[6]=__hadd2(c[6],u2h(v.z)); c[7]=__hadd2(c[7],u2h(v.w));
    v = p[2];
    c[8]=__hadd2(c[8],u2h(v.x)); c[9]=__hadd2(c[9],u2h(v.y));
    c[10]=__hadd2(c[10],u2h(v.z)); c[11]=__hadd2(c[11],u2h(v.w));
    c[12]=__hadd2(c[12], base[12]);
}
__device__ __forceinline__ void fmarow13(__half2 c[13], const __half2* base, __half2 m) {
    const uint4* p = reinterpret_cast<const uint4*>(base);
    uint4 v;
    v = p[0];
    c[0]=__hfma2(m,u2h(v.x),c[0]); c[1]=__hfma2(m,u2h(v.y),c[1]);
    c[2]=__hfma2(m,u2h(v.z),c[2]); c[3]=__hfma2(m,u2h(v.w),c[3]);
    v = p[1];
    c[4]=__hfma2(m,u2h(v.x),c[4]); c[5]=__hfma2(m,u2h(v.y),c[5]);
    c[6]=__hfma2(m,u2h(v.z),c[6]); c[7]=__hfma2(m,u2h(v.w),c[7]);
    v = p[2];
    c[8]=__hfma2(m,u2h(v.x),c[8]); c[9]=__hfma2(m,u2h(v.y),c[9]);
    c[10]=__hfma2(m,u2h(v.z),c[10]); c[11]=__hfma2(m,u2h(v.w),c[11]);
    c[12]=__hfma2(m, base[12], c[12]);
}

// col in registers; xch aliases lin (entry barrier drains lin reads) and the
// output buffer (pre-output barrier drains R-tap row reads).
__device__ __forceinline__ void smooth_rounds(__half2 col[19], __half2* xch, int t) {
    const __half2 T2 = __float2half2_rn(2.0f);
    const __half2 T3 = __float2half2_rn(3.0f);
    const __half2 INV = __float2half2_rn(1.0f/729.0f);
    int x = t % 19, y = t / 19;
    bool own = t < NROW;
    __half2* myrow = xch + t * XROW;

    __half2 a[17];
    #pragma unroll
    for (int z = 0; z < 17; z++) a[z] = hmax3(col[z], col[z+1], col[z+2]);

    __syncthreads();   // drain lin reads (xch aliased)

    // R1 (FUSED): max over x AND y — 3x3 neighborhood, 8 neighbor rows
    if (own) write17(myrow, a);
    __syncthreads();
    if (own && x < 17 && y < 17) {
        maxrow17(a, xch + (t+1)*XROW);
        maxrow17(a, xch + (t+2)*XROW);
        maxrow17(a, xch + (t+19)*XROW);
        maxrow17(a, xch + (t+20)*XROW);
        maxrow17(a, xch + (t+21)*XROW);
        maxrow17(a, xch + (t+38)*XROW);
        maxrow17(a, xch + (t+39)*XROW);
        maxrow17(a, xch + (t+40)*XROW);
    }
    __syncthreads();

    // 5-tap over z (registers)
    __half2 c[13];
    #pragma unroll
    for (int z = 0; z < 13; z++) {
        __half2 s = __hadd2(a[z], a[z+4]);
        s = __hfma2(T2, __hadd2(a[z+1], a[z+3]), s);
        c[z] = __hfma2(T3, a[z+2], s);
    }

    // R2: 5-tap over x
    if (own) write13(myrow, c);
    __syncthreads();
    if (own && x < 13) {
        fmarow13(c, xch + (t+1)*XROW, T2);
        fmarow13(c, xch + (t+2)*XROW, T3);
        fmarow13(c, xch + (t+3)*XROW, T2);
        addrow13(c, xch + (t+4)*XROW);
    }
    __syncthreads();

    // R3: 5-tap over y
    if (own) write13(myrow, c);
    __syncthreads();
    if (own && x < 13 && y < 13) {
        fmarow13(c, xch + (t+19)*XROW, T2);
        fmarow13(c, xch + (t+38)*XROW, T3);
        fmarow13(c, xch + (t+57)*XROW, T2);
        addrow13(c, xch + (t+76)*XROW);
    }
    __syncthreads();   // drain row reads before output overwrites xch
    if (own && x < 13 && y < 13) {
        int base = (x*13 + y)*13;
        #pragma unroll
        for (int z = 0; z < 13; z++) xch[base + z] = __hmul2(c[z], INV);
    }
}

__device__ __forceinline__ void build_col(const __half2* lin, __half2 col[19], int t) {
    if (t < NROW) {
        int x = t % 19, y = t / 19;
        int cx = min(max(x - 3, 0), 12);
        int cy = min(max(y - 3, 0), 12);
        const __half2* src = lin + (cx*13 + cy)*13;
        __half2 vv[13];
        #pragma unroll
        for (int z = 0; z < 13; z++) vv[z] = src[z];
        #pragma unroll
        for (int pz = 0; pz < 19; pz++) col[pz] = vv[min(max(pz - 3, 0), 12)];
    }
}

__device__ __forceinline__ void store_pair(const __half2* outb, __half* d0, __half* d1,
                                           int t) {
    const __half2 Z = __float2half2_rn(0.0f);
    for (int i = t; i < VPAD/2; i += PT) {
        int i0 = 2*i;
        __half2 v0 = (i0     < NVOX) ? outb[i0]     : Z;
        __half2 v1 = (i0 + 1 < NVOX) ? outb[i0 + 1] : Z;
        *reinterpret_cast<__half2*>(d0 + i0) = __lows2half2(v0, v1);
        *reinterpret_cast<__half2*>(d1 + i0) = __highs2half2(v0, v1);
    }
}

// ---------------- Kernel A: S1 = smooth(a1 + a0*cost), paired ----------------
__global__ void __launch_bounds__(PT, 5) k_smooth1(
    const float* __restrict__ cost, const float* __restrict__ alpha) {
    __shared__ __align__(16) __half2 xch[XCHW];
    int p = blockIdx.x, t = threadIdx.x;
    float a0 = alpha[0], a1 = alpha[1];
    const float* s0 = cost + (size_t)(2*p) * NVOX;
    const float* s1 = cost + (size_t)(2*p + 1) * NVOX;

    for (int v = t; v < NVOX; v += PT)
        xch[v] = __floats2half2_rn(a1 + a0 * __ldg(s0 + v), a1 + a0 * __ldg(s1 + v));
    __syncthreads();

    __half2 col[19];
    build_col(xch, col, t);
    smooth_rounds(col, xch, t);
    __syncthreads();
    store_pair(xch, g_S1 + (size_t)(2*p)*VPAD, g_S1 + (size_t)(2*p+1)*VPAD, t);
}

// ------- Kernel B: c2 = blend(cost, gatherW(S1)); S2 = smooth(c2), paired -------
// Gather: R12-style — 276 threads, both volumes, res[2][8] packed into 2 STS.128.
// No reg cap (ptxas free; occupancy smem/reg-limited ~4 blocks).
__global__ void __launch_bounds__(PT) k_gather_smooth(
    const float* __restrict__ cost, const int* __restrict__ knn,
    const float* __restrict__ dist, const float* __restrict__ alpha) {
    __shared__ __align__(16) __half2 xch[XCHW];
    __shared__ float wsh[2][KNN];
    __shared__ int   nbsh[2][KNN];
    __shared__ float sninv[2];
    int p = blockIdx.x, t = threadIdx.x;

    if (t < 16) {
        int h = t >> 3, k = t & 7;
        int n = 2*p + h;
        wsh[h][k] = __expf(-__ldg(&dist[n*KNN + k]) * (1.0f/200.0f)); // 2*SIGMA^2=200
        nbsh[h][k] = __ldg(&knn[n*KNN + k]);
    }
    __syncthreads();
    if (t < 2) {
        float s = 0.0f;
        #pragma unroll
        for (int k = 0; k < KNN; k++) s += wsh[t][k];
        sninv[t] = 1.0f / s;
    }
    __syncthreads();

    float a0 = alpha[0], a1 = alpha[1], a2 = alpha[2], a3 = alpha[3], a4 = alpha[4];

    if (t < NCHUNK) {
        int cch = t, vbase = cch * 8;
        float res[2][8];
        #pragma unroll
        for (int h = 0; h < 2; h++) {
            float acc[8];
            #pragma unroll
            for (int j = 0; j < 8; j++) acc[j] = 0.0f;
            #pragma unroll
            for (int k = 0; k < KNN; k++) {
                float w = wsh[h][k];
                const uint4* np = reinterpret_cast<const uint4*>(
                    g_S1 + (size_t)nbsh[h][k] * VPAD);
                uint4 raw = __ldg(&np[cch]);
                float2 f0 = __half22float2(u2h(raw.x));
                float2 f1 = __half22float2(u2h(raw.y));
                float2 f2 = __half22float2(u2h(raw.z));
                float2 f3 = __half22float2(u2h(raw.w));
                acc[0] += w*f0.x; acc[1] += w*f0.y;
                acc[2] += w*f1.x; acc[3] += w*f1.y;
                acc[4] += w*f2.x; acc[5] += w*f2.y;
                acc[6] += w*f3.x; acc[7] += w*f3.y;
            }
            const float* src = cost + (size_t)(2*p + h) * NVOX;
            float ninv = sninv[h];
            #pragma unroll
            for (int j = 0; j < 8; j++) {
                int v = vbase + j;
                float c1 = (v < NVOX) ? (a1 + a0 * __ldg(&src[v])) : 0.0f;
                res[h][j] = a4 + a2*c1 + a3*(acc[j]*ninv);
            }
        }
        uint4 w0, w1;
        w0.x = h2u(__floats2half2_rn(res[0][0], res[1][0]));
        w0.y = h2u(__floats2half2_rn(res[0][1], res[1][1]));
        w0.z = h2u(__floats2half2_rn(res[0][2], res[1][2]));
        w0.w = h2u(__floats2half2_rn(res[0][3], res[1][3]));
        w1.x = h2u(__floats2half2_rn(res[0][4], res[1][4]));
        w1.y = h2u(__floats2half2_rn(res[0][5], res[1][5]));
        w1.z = h2u(__floats2half2_rn(res[0][6], res[1][6]));
        w1.w = h2u(__floats2half2_rn(res[0][7], res[1][7]));
        uint4* lp = reinterpret_cast<uint4*>(xch);
        lp[cch*2]     = w0;
        lp[cch*2 + 1] = w1;
    }
    __syncthreads();

    __half2 col[19];
    build_col(xch, col, t);
    smooth_rounds(col, xch, t);
    __syncthreads();
    store_pair(xch, g_S2 + (size_t)(2*p)*VPAD, g_S2 + (size_t)(2*p+1)*VPAD, t);
}

// ------- Kernel C: out = a5 * gatherW(S2) / norm, paired + coalesced stores -------
__global__ void __launch_bounds__(CT) k_gather_out(
    const int* __restrict__ knn, const float* __restrict__ dist,
    const float* __restrict__ alpha, float* __restrict__ out) {
    __shared__ float wsh[2][KNN];
    __shared__ int   nbsh[2][KNN];
    __shared__ float sscale[2];
    __shared__ float obuf[2][VPAD];
    int p = blockIdx.x;
    int tid = threadIdx.x;

    if (tid < 16) {
        int h = tid >> 3, k = tid & 7;
        int n = 2*p + h;
        wsh[h][k] = __expf(-__ldg(&dist[n*KNN + k]) * (1.0f/200.0f));
        nbsh[h][k] = __ldg(&knn[n*KNN + k]);
    }
    __syncthreads();
    if (tid < 2) {
        float s = 0.0f;
        #pragma unroll
        for (int k = 0; k < KNN; k++) s += wsh[tid][k];
        sscale[tid] = alpha[5] / s;
    }
    __syncthreads();

    if (tid < 2*NCHUNK) {
        int h = tid / NCHUNK;
        int cch = tid - h*NCHUNK;
        float acc[8];
        #pragma unroll
        for (int j = 0; j < 8; j++) acc[j] = 0.0f;
        #pragma unroll
        for (int k = 0; k < KNN; k++) {
            float w = wsh[h][k];
            const uint4* np = reinterpret_cast<const uint4*>(
                g_S2 + (size_t)nbsh[h][k] * VPAD);
            uint4 raw = __ldg(&np[cch]);
            float2 f0 = __half22float2(u2h(raw.x));
            float2 f1 = __half22float2(u2h(raw.y));
            float2 f2 = __half22float2(u2h(raw.z));
            float2 f3 = __half22float2(u2h(raw.w));
            acc[0] += w*f0.x; acc[1] += w*f0.y;
            acc[2] += w*f1.x; acc[3] += w*f1.y;
            acc[4] += w*f2.x; acc[5] += w*f2.y;
            acc[6] += w*f3.x; acc[7] += w*f3.y;
        }
        float sc = sscale[h];
        int vbase = cch * 8;
        #pragma unroll
        for (int j = 0; j < 8; j++) obuf[h][vbase + j] = acc[j] * sc;
    }
    __syncthreads();

    float* d0 = out + (size_t)(2*p) * NVOX;
    float* d1 = out + (size_t)(2*p + 1) * NVOX;
    for (int i = tid; i < NVOX; i += CT) {
        d0[i] = obuf[0][i];
        d1[i] = obuf[1][i];
    }
}

extern "C" void kernel_launch(void* const* d_in, const int* in_sizes, int n_in,
                              void* d_out, int out_size) {
    const float* cost  = (const float*)d_in[0];
    const int*   knn   = (const int*)d_in[1];
    const float* dist  = (const float*)d_in[2];
    const float* alpha = (const float*)d_in[3];
    float* out = (float*)d_out;
    int N = in_sizes[0] / NVOX;   // 10000
    int NP = N / 2;               // 5000 volume pairs

    k_smooth1<<<NP, PT>>>(cost, alpha);
    k_gather_smooth<<<NP, PT>>>(cost, knn, dist, alpha);
    k_gather_out<<<NP, CT>>>(knn, dist, alpha, out);
}

// round 17
// speedup vs baseline: 1.1691x; 1.0725x over previous
#include <cuda_runtime.h>
#include <cuda_fp16.h>

// deeds_graph: N=10000 volumes of 13^3, K=8 neighbors. One half2 pair per
// 384-thread block. lin aliased into xch (28.9KB smem). Smooth cross-thread
// passes are smem rounds on z-contiguous rows (stride 20 half2 = 80B,
// LDS.128/STS.128 conflict-free); max rounds SPLIT (R16 fusion regressed:
// byte-bound, 8-row read > 2+2). cost reads use __ldcs (evict-first stream)
// to keep S1/S2 L2-resident for the gathers.
// S1 = smooth(a1 + a0*cost); c2 = a4 + a2*(a1+a0*cost) + a3*gatherW(S1)/norm;
// S2 = smooth(c2); out = a5*gatherW(S2)/norm.
// smooth = edge-pad(3) -> max3^3 -> (5-tap [1,2,3,2,1]/9)^3 (separable).

#define NVOX 2197          // 13^3
#define VPAD 2208          // padded halves per volume (16B chunks)
#define NCHUNK 276         // VPAD/8
#define NMAX 10000
#define KNN  8
#define NROW 361           // 19*19 padded rows
#define XROW 20            // half2 words per row (80B)
#define XCHW (NROW*XROW)   // 7220 half2 (28.9KB), lin[VPAD] aliased in
#define PT   384           // threads per block
#define CT 576             // kernel C block

__device__ __half g_S1[(size_t)NMAX * VPAD];
__device__ __half g_S2[(size_t)NMAX * VPAD];

__device__ __forceinline__ unsigned h2u(__half2 v) { return *reinterpret_cast<unsigned*>(&v); }
__device__ __forceinline__ __half2 u2h(unsigned u) { return *reinterpret_cast<__half2*>(&u); }
__device__ __forceinline__ uint4 pk4(__half2 a, __half2 b, __half2 c, __half2 d) {
    return make_uint4(h2u(a), h2u(b), h2u(c), h2u(d));
}
__device__ __forceinline__ __half2 hmax3(__half2 a, __half2 b, __half2 c) {
    return __hmax2(__hmax2(a, b), c);
}

__device__ __forceinline__ void write17(__half2* rp, const __half2 a[17]) {
    uint4* p = reinterpret_cast<uint4*>(rp);
    p[0] = pk4(a[0], a[1], a[2], a[3]);
    p[1] = pk4(a[4], a[5], a[6], a[7]);
    p[2] = pk4(a[8], a[9], a[10], a[11]);
    p[3] = pk4(a[12], a[13], a[14], a[15]);
    reinterpret_cast<unsigned*>(rp)[16] = h2u(a[16]);
}
__device__ __forceinline__ void write13(__half2* rp, const __half2 c[13]) {
    uint4* p = reinterpret_cast<uint4*>(rp);
    p[0] = pk4(c[0], c[1], c[2], c[3]);
    p[1] = pk4(c[4], c[5], c[6], c[7]);
    p[2] = pk4(c[8], c[9], c[10], c[11]);
    reinterpret_cast<unsigned*>(rp)[12] = h2u(c[12]);
}
__device__ __forceinline__ void maxrow17(__half2 a[17], const __half2* base) {
    const uint4* p = reinterpret_cast<const uint4*>(base);
    uint4 v;
    v = p[0];
    a[0]=__hmax2(a[0],u2h(v.x)); a[1]=__hmax2(a[1],u2h(v.y));
    a[2]=__hmax2(a[2],u2h(v.z)); a[3]=__hmax2(a[3],u2h(v.w));
    v = p[1];
    a[4]=__hmax2(a[4],u2h(v.x)); a[5]=__hmax2(a[5],u2h(v.y));
    a[6]=__hmax2(a[6],u2h(v.z)); a[7]=__hmax2(a[7],u2h(v.w));
    v = p[2];
    a[8]=__hmax2(a[8],u2h(v.x)); a[9]=__hmax2(a[9],u2h(v.y));
    a[10]=__hmax2(a[10],u2h(v.z)); a[11]=__hmax2(a[11],u2h(v.w));
    v = p[3];
    a[12]=__hmax2(a[12],u2h(v.x)); a[13]=__hmax2(a[13],u2h(v.y));
    a[14]=__hmax2(a[14],u2h(v.z)); a[15]=__hmax2(a[15],u2h(v.w));
    a[16]=__hmax2(a[16], base[16]);
}
__device__ __forceinline__ void addrow13(__half2 c[13], const __half2* base) {
    const uint4* p = reinterpret_cast<const uint4*>(base);
    uint4 v;
    v = p[0];
    c[0]=__hadd2(c[0],u2h(v.x)); c[1]=__hadd2(c[1],u2h(v.y));
    c[2]=__hadd2(c[2],u2h(v.z)); c[3]=__hadd2(c[3],u2h(v.w));
    v = p[1];
    c[4]=__hadd2(c[4],u2h(v.x)); c[5]=__hadd2(c[5],u2h(v.y));
    c[6]=__hadd2(c[6],u2h(v.z)); c[7]=__hadd2(c[7],u2h(v.w));
    v = p[2];
    c[8]=__hadd2(c[8],u2h(v.x)); c[9]=__hadd2(c[9],u2h(v.y));
    c[10]=__hadd2(c[10],u2h(v.z)); c[11]=__hadd2(c[11],u2h(v.w));
    c[12]=__hadd2(c[12], base[12]);
}
__device__ __forceinline__ void fmarow13(__half2 c[13], const __half2* base, __half2 m) {
    const uint4* p = reinterpret_cast<const uint4*>(base);
    uint4 v;
    v = p[0];
    c[0]=__hfma2(m,u2h(v.x),c[0]); c[1]=__hfma2(m,u2h(v.y),c[1]);
    c[2]=__hfma2(m,u2h(v.z),c[2]); c[3]=__hfma2(m,u2h(v.w),c[3]);
    v = p[1];
    c[4]=__hfma2(m,u2h(v.x),c[4]); c[5]=__hfma2(m,u2h(v.y),c[5]);
    c[6]=__hfma2(m,u2h(v.z),c[6]); c[7]=__hfma2(m,u2h(v.w),c[7]);
    v = p[2];
    c[8]=__hfma2(m,u2h(v.x),c[8]); c[9]=__hfma2(m,u2h(v.y),c[9]);
    c[10]=__hfma2(m,u2h(v.z),c[10]); c[11]=__hfma2(m,u2h(v.w),c[11]);
    c[12]=__hfma2(m, base[12], c[12]);
}

// col in registers; xch aliases lin (entry barrier drains lin reads) and the
// output buffer (pre-output barrier drains tap-round row reads).
__device__ __forceinline__ void smooth_rounds(__half2 col[19], __half2* xch, int t) {
    const __half2 T2 = __float2half2_rn(2.0f);
    const __half2 T3 = __float2half2_rn(3.0f);
    const __half2 INV = __float2half2_rn(1.0f/729.0f);
    int x = t % 19, y = t / 19;
    bool own = t < NROW;
    __half2* myrow = xch + t * XROW;

    __half2 a[17];
    #pragma unroll
    for (int z = 0; z < 17; z++) a[z] = hmax3(col[z], col[z+1], col[z+2]);

    __syncthreads();   // drain lin reads (xch aliased)

    // R1: max over x
    if (own) write17(myrow, a);
    __syncthreads();
    if (own && x < 17) {
        maxrow17(a, xch + (t+1)*XROW);
        maxrow17(a, xch + (t+2)*XROW);
    }
    __syncthreads();

    // R2: max over y
    if (own) write17(myrow, a);
    __syncthreads();
    if (own && y < 17) {
        maxrow17(a, xch + (t+19)*XROW);
        maxrow17(a, xch + (t+38)*XROW);
    }
    __syncthreads();

    // 5-tap over z (registers)
    __half2 c[13];
    #pragma unroll
    for (int z = 0; z < 13; z++) {
        __half2 s = __hadd2(a[z], a[z+4]);
        s = __hfma2(T2, __hadd2(a[z+1], a[z+3]), s);
        c[z] = __hfma2(T3, a[z+2], s);
    }

    // R3: 5-tap over x
    if (own) write13(myrow, c);
    __syncthreads();
    if (own && x < 13) {
        fmarow13(c, xch + (t+1)*XROW, T2);
        fmarow13(c, xch + (t+2)*XROW, T3);
        fmarow13(c, xch + (t+3)*XROW, T2);
        addrow13(c, xch + (t+4)*XROW);
    }
    __syncthreads();

    // R4: 5-tap over y
    if (own) write13(myrow, c);
    __syncthreads();
    if (own && x < 13 && y < 13) {
        fmarow13(c, xch + (t+19)*XROW, T2);
        fmarow13(c, xch + (t+38)*XROW, T3);
        fmarow13(c, xch + (t+57)*XROW, T2);
        addrow13(c, xch + (t+76)*XROW);
    }
    __syncthreads();   // drain row reads before output overwrites xch
    if (own && x < 13 && y < 13) {
        int base = (x*13 + y)*13;
        #pragma unroll
        for (int z = 0; z < 13; z++) xch[base + z] = __hmul2(c[z], INV);
    }
}

__device__ __forceinline__ void build_col(const __half2* lin, __half2 col[19], int t) {
    if (t < NROW) {
        int x = t % 19, y = t / 19;
        int cx = min(max(x - 3, 0), 12);
        int cy = min(max(y - 3, 0), 12);
        const __half2* src = lin + (cx*13 + cy)*13;
        __half2 vv[13];
        #pragma unroll
        for (int z = 0; z < 13; z++) vv[z] = src[z];
        #pragma unroll
        for (int pz = 0; pz < 19; pz++) col[pz] = vv[min(max(pz - 3, 0), 12)];
    }
}

__device__ __forceinline__ void store_pair(const __half2* outb, __half* d0, __half* d1,
                                           int t) {
    const __half2 Z = __float2half2_rn(0.0f);
    for (int i = t; i < VPAD/2; i += PT) {
        int i0 = 2*i;
        __half2 v0 = (i0     < NVOX) ? outb[i0]     : Z;
        __half2 v1 = (i0 + 1 < NVOX) ? outb[i0 + 1] : Z;
        *reinterpret_cast<__half2*>(d0 + i0) = __lows2half2(v0, v1);
        *reinterpret_cast<__half2*>(d1 + i0) = __highs2half2(v0, v1);
    }
}

// ---------------- Kernel A: S1 = smooth(a1 + a0*cost), paired ----------------
__global__ void __launch_bounds__(PT, 5) k_smooth1(
    const float* __restrict__ cost, const float* __restrict__ alpha) {
    __shared__ __align__(16) __half2 xch[XCHW];
    int p = blockIdx.x, t = threadIdx.x;
    float a0 = alpha[0], a1 = alpha[1];
    const float* s0 = cost + (size_t)(2*p) * NVOX;
    const float* s1 = cost + (size_t)(2*p + 1) * NVOX;

    for (int v = t; v < NVOX; v += PT)
        xch[v] = __floats2half2_rn(a1 + a0 * __ldcs(s0 + v), a1 + a0 * __ldcs(s1 + v));
    __syncthreads();

    __half2 col[19];
    build_col(xch, col, t);
    smooth_rounds(col, xch, t);
    __syncthreads();
    store_pair(xch, g_S1 + (size_t)(2*p)*VPAD, g_S1 + (size_t)(2*p+1)*VPAD, t);
}

// ------- Kernel B: c2 = blend(cost, gatherW(S1)); S2 = smooth(c2), paired -------
// Gather: 276 threads, both volumes, res[2][8] packed into 2 STS.128.
__global__ void __launch_bounds__(PT) k_gather_smooth(
    const float* __restrict__ cost, const int* __restrict__ knn,
    const float* __restrict__ dist, const float* __restrict__ alpha) {
    __shared__ __align__(16) __half2 xch[XCHW];
    __shared__ float wsh[2][KNN];
    __shared__ int   nbsh[2][KNN];
    __shared__ float sninv[2];
    int p = blockIdx.x, t = threadIdx.x;

    if (t < 16) {
        int h = t >> 3, k = t & 7;
        int n = 2*p + h;
        wsh[h][k] = __expf(-__ldg(&dist[n*KNN + k]) * (1.0f/200.0f)); // 2*SIGMA^2=200
        nbsh[h][k] = __ldg(&knn[n*KNN + k]);
    }
    __syncthreads();
    if (t < 2) {
        float s = 0.0f;
        #pragma unroll
        for (int k = 0; k < KNN; k++) s += wsh[t][k];
        sninv[t] = 1.0f / s;
    }
    __syncthreads();

    float a0 = alpha[0], a1 = alpha[1], a2 = alpha[2], a3 = alpha[3], a4 = alpha[4];

    if (t < NCHUNK) {
        int cch = t, vbase = cch * 8;
        float res[2][8];
        #pragma unroll
        for (int h = 0; h < 2; h++) {
            float acc[8];
            #pragma unroll
            for (int j = 0; j < 8; j++) acc[j] = 0.0f;
            #pragma unroll
            for (int k = 0; k < KNN; k++) {
                float w = wsh[h][k];
                const uint4* np = reinterpret_cast<const uint4*>(
                    g_S1 + (size_t)nbsh[h][k] * VPAD);
                uint4 raw = __ldg(&np[cch]);
                float2 f0 = __half22float2(u2h(raw.x));
                float2 f1 = __half22float2(u2h(raw.y));
                float2 f2 = __half22float2(u2h(raw.z));
                float2 f3 = __half22float2(u2h(raw.w));
                acc[0] += w*f0.x; acc[1] += w*f0.y;
                acc[2] += w*f1.x; acc[3] += w*f1.y;
                acc[4] += w*f2.x; acc[5] += w*f2.y;
                acc[6] += w*f3.x; acc[7] += w*f3.y;
            }
            const float* src = cost + (size_t)(2*p + h) * NVOX;
            float ninv = sninv[h];
            #pragma unroll
            for (int j = 0; j < 8; j++) {
                int v = vbase + j;
                float c1 = (v < NVOX) ? (a1 + a0 * __ldcs(&src[v])) : 0.0f;
                res[h][j] = a4 + a2*c1 + a3*(acc[j]*ninv);
            }
        }
        uint4 w0, w1;
        w0.x = h2u(__floats2half2_rn(res[0][0], res[1][0]));
        w0.y = h2u(__floats2half2_rn(res[0][1], res[1][1]));
        w0.z = h2u(__floats2half2_rn(res[0][2], res[1][2]));
        w0.w = h2u(__floats2half2_rn(res[0][3], res[1][3]));
        w1.x = h2u(__floats2half2_rn(res[0][4], res[1][4]));
        w1.y = h2u(__floats2half2_rn(res[0][5], res[1][5]));
        w1.z = h2u(__floats2half2_rn(res[0][6], res[1][6]));
        w1.w = h2u(__floats2half2_rn(res[0][7], res[1][7]));
        uint4* lp = reinterpret_cast<uint4*>(xch);
        lp[cch*2]     = w0;
        lp[cch*2 + 1] = w1;
    }
    __syncthreads();

    __half2 col[19];
    build_col(xch, col, t);
    smooth_rounds(col, xch, t);
    __syncthreads();
    store_pair(xch, g_S2 + (size_t)(2*p)*VPAD, g_S2 + (size_t)(2*p+1)*VPAD, t);
}

// ------- Kernel C: out = a5 * gatherW(S2) / norm, paired + coalesced stores -------
__global__ void __launch_bounds__(CT) k_gather_out(
    const int* __restrict__ knn, const float* __restrict__ dist,
    const float* __restrict__ alpha, float* __restrict__ out) {
    __shared__ float wsh[2][KNN];
    __shared__ int   nbsh[2][KNN];
    __shared__ float sscale[2];
    __shared__ float obuf[2][VPAD];
    int p = blockIdx.x;
    int tid = threadIdx.x;

    if (tid < 16) {
        int h = tid >> 3, k = tid & 7;
        int n = 2*p + h;
        wsh[h][k] = __expf(-__ldg(&dist[n*KNN + k]) * (1.0f/200.0f));
        nbsh[h][k] = __ldg(&knn[n*KNN + k]);
    }
    __syncthreads();
    if (tid < 2) {
        float s = 0.0f;
        #pragma unroll
        for (int k = 0; k < KNN; k++) s += wsh[tid][k];
        sscale[tid] = alpha[5] / s;
    }
    __syncthreads();

    if (tid < 2*NCHUNK) {
        int h = tid / NCHUNK;
        int cch = tid - h*NCHUNK;
        float acc[8];
        #pragma unroll
        for (int j = 0; j < 8; j++) acc[j] = 0.0f;
        #pragma unroll
        for (int k = 0; k < KNN; k++) {
            float w = wsh[h][k];
            const uint4* np = reinterpret_cast<const uint4*>(
                g_S2 + (size_t)nbsh[h][k] * VPAD);
            uint4 raw = __ldg(&np[cch]);
            float2 f0 = __half22float2(u2h(raw.x));
            float2 f1 = __half22float2(u2h(raw.y));
            float2 f2 = __half22float2(u2h(raw.z));
            float2 f3 = __half22float2(u2h(raw.w));
            acc[0] += w*f0.x; acc[1] += w*f0.y;
            acc[2] += w*f1.x; acc[3] += w*f1.y;
            acc[4] += w*f2.x; acc[5] += w*f2.y;
            acc[6] += w*f3.x; acc[7] += w*f3.y;
        }
        float sc = sscale[h];
        int vbase = cch * 8;
        #pragma unroll
        for (int j = 0; j < 8; j++) obuf[h][vbase + j] = acc[j] * sc;
    }
    __syncthreads();

    float* d0 = out + (size_t)(2*p) * NVOX;
    float* d1 = out + (size_t)(2*p + 1) * NVOX;
    for (int i = tid; i < NVOX; i += CT) {
        d0[i] = obuf[0][i];
        d1[i] = obuf[1][i];
    }
}

extern "C" void kernel_launch(void* const* d_in, const int* in_sizes, int n_in,
                              void* d_out, int out_size) {
    const float* cost  = (const float*)d_in[0];
    const int*   knn   = (const int*)d_in[1];
    const float* dist  = (const float*)d_in[2];
    const float* alpha = (const float*)d_in[3];
    float* out = (float*)d_out;
    int N = in_sizes[0] / NVOX;   // 10000
    int NP = N / 2;               // 5000 volume pairs

    k_smooth1<<<NP, PT>>>(cost, alpha);
    k_gather_smooth<<<NP, PT>>>(cost, knn, dist, alpha);
    k_gather_out<<<NP, CT>>>(knn, dist, alpha, out);
}